// round 16
// baseline (speedup 1.0000x reference)
#include <cuda_runtime.h>

#define HID   128
#define NSTEP 128
#define MROWS 16
#define NTHR  256
#define WSTR  132              // weight row stride (floats): 128 + 4 swizzle spare
#define ASTR  28               // act row stride (floats): 16 data + 12 swizzle spare
#define NEGS  0.2f

// ---- dynamic smem layout (float offsets) ----
#define WB0   0                      // 128*WSTR = 16896 floats
#define WB1   16896
#define HB_F  33792                  // 128*ASTR = 3584 floats each
#define HT_F  (HB_F + HID * ASTR)
#define HB_P  (HT_F + HID * ASTR)
#define HT_P  (HB_P + HID * ASTR)
#define XST   (HT_P + HID * ASTR)    // xsT[12][16]
#define DSO   (XST + 192)            // delta[16]
#define SMEM_FLOATS (DSO + 16)
#define SMEM_BYTES  (SMEM_FLOATS * 4)

typedef unsigned long long u64;

// ---------- packed fp32x2 helpers ----------
__device__ __forceinline__ u64 ffma2(u64 x, u64 y, u64 c) {
    u64 d;
    asm("fma.rn.f32x2 %0, %1, %2, %3;" : "=l"(d) : "l"(x), "l"(y), "l"(c));
    return d;
}
__device__ __forceinline__ u64 pack2(float lo, float hi) {
    u64 d;
    asm("mov.b64 %0, {%1, %2};" : "=l"(d) : "f"(lo), "f"(hi));
    return d;
}
__device__ __forceinline__ void unpack2(u64 v, float& lo, float& hi) {
    asm("mov.b64 {%0, %1}, %2;" : "=f"(lo), "=f"(hi) : "l"(v));
}

// ---------- cp.async ----------
__device__ __forceinline__ void cp_async16(unsigned dst, const void* src) {
    asm volatile("cp.async.cg.shared.global [%0], [%1], 16;" :: "r"(dst), "l"(src));
}
__device__ __forceinline__ void cp_commit() {
    asm volatile("cp.async.commit_group;" ::: "memory");
}
__device__ __forceinline__ void cp_wait_all() {
    asm volatile("cp.async.wait_group 0;" ::: "memory");
}

// act address: row r, col m. Swizzle ((r>>3)&3)*4 separates rows 16 apart
// (mainloop kq-pair reads) and rows 8 apart (epilogue stores).
__device__ __forceinline__ int act_addr(int r, int m) {
    return r * ASTR + ((r >> 3) & 3) * 4 + m;
}

// 64KB weight matrix -> smem, swizzled: row k at k*WSTR + ((k>>4)&1)*4.
__device__ __forceinline__ void prefetch_w(const float* __restrict__ src,
                                           float* dstf, int tid) {
    unsigned dstb = (unsigned)__cvta_generic_to_shared(dstf);
#pragma unroll
    for (int i = 0; i < 16; ++i) {
        const int idx = tid + i * NTHR;          // float4 index 0..4095
        const int k   = idx >> 5;
        const int q   = idx & 31;
        const int dst = k * WSTR + ((k >> 4) & 1) * 4 + q * 4;
        cp_async16(dstb + (unsigned)dst * 4, (const char*)src + (size_t)idx * 16);
    }
}

// Accumulators: A[p][m] = f32x2 (row j0+2p, row j0+2p+1) at m-col m0+m.
struct Acc { u64 a[4][8]; };
__device__ __forceinline__ void acc_zero(Acc& A) {
#pragma unroll
    for (int p = 0; p < 4; ++p)
#pragma unroll
        for (int m = 0; m < 8; ++m) A.a[p][m] = 0ull;
}

// Partial GEMM over this lane's 16-row k-chunk (two 8-row affine sub-blocks:
// the act swizzle flips at kk=8, so ap2 is a second precomputed base).
__device__ __forceinline__ void mm_half(Acc& A, const float* __restrict__ wp,
                                        const float* __restrict__ ap) {
#pragma unroll
    for (int kk = 0; kk < 8; ++kk) {
        const float4 wA = *reinterpret_cast<const float4*>(wp + kk * WSTR);
        const float4 wB = *reinterpret_cast<const float4*>(wp + kk * WSTR + 4);
        const float4 aA = *reinterpret_cast<const float4*>(ap + kk * ASTR);
        const float4 aB = *reinterpret_cast<const float4*>(ap + kk * ASTR + 4);
        const u64 wp0 = pack2(wA.x, wA.y);   // natural register pairs
        const u64 wp1 = pack2(wA.z, wA.w);
        const u64 wp2 = pack2(wB.x, wB.y);
        const u64 wp3 = pack2(wB.z, wB.w);
        const u64 a0 = pack2(aA.x, aA.x);
        const u64 a1 = pack2(aA.y, aA.y);
        const u64 a2 = pack2(aA.z, aA.z);
        const u64 a3 = pack2(aA.w, aA.w);
        const u64 a4 = pack2(aB.x, aB.x);
        const u64 a5 = pack2(aB.y, aB.y);
        const u64 a6 = pack2(aB.z, aB.z);
        const u64 a7 = pack2(aB.w, aB.w);
        A.a[0][0] = ffma2(wp0, a0, A.a[0][0]);
        A.a[0][1] = ffma2(wp0, a1, A.a[0][1]);
        A.a[0][2] = ffma2(wp0, a2, A.a[0][2]);
        A.a[0][3] = ffma2(wp0, a3, A.a[0][3]);
        A.a[0][4] = ffma2(wp0, a4, A.a[0][4]);
        A.a[0][5] = ffma2(wp0, a5, A.a[0][5]);
        A.a[0][6] = ffma2(wp0, a6, A.a[0][6]);
        A.a[0][7] = ffma2(wp0, a7, A.a[0][7]);
        A.a[1][0] = ffma2(wp1, a0, A.a[1][0]);
        A.a[1][1] = ffma2(wp1, a1, A.a[1][1]);
        A.a[1][2] = ffma2(wp1, a2, A.a[1][2]);
        A.a[1][3] = ffma2(wp1, a3, A.a[1][3]);
        A.a[1][4] = ffma2(wp1, a4, A.a[1][4]);
        A.a[1][5] = ffma2(wp1, a5, A.a[1][5]);
        A.a[1][6] = ffma2(wp1, a6, A.a[1][6]);
        A.a[1][7] = ffma2(wp1, a7, A.a[1][7]);
        A.a[2][0] = ffma2(wp2, a0, A.a[2][0]);
        A.a[2][1] = ffma2(wp2, a1, A.a[2][1]);
        A.a[2][2] = ffma2(wp2, a2, A.a[2][2]);
        A.a[2][3] = ffma2(wp2, a3, A.a[2][3]);
        A.a[2][4] = ffma2(wp2, a4, A.a[2][4]);
        A.a[2][5] = ffma2(wp2, a5, A.a[2][5]);
        A.a[2][6] = ffma2(wp2, a6, A.a[2][6]);
        A.a[2][7] = ffma2(wp2, a7, A.a[2][7]);
        A.a[3][0] = ffma2(wp3, a0, A.a[3][0]);
        A.a[3][1] = ffma2(wp3, a1, A.a[3][1]);
        A.a[3][2] = ffma2(wp3, a2, A.a[3][2]);
        A.a[3][3] = ffma2(wp3, a3, A.a[3][3]);
        A.a[3][4] = ffma2(wp3, a4, A.a[3][4]);
        A.a[3][5] = ffma2(wp3, a5, A.a[3][5]);
        A.a[3][6] = ffma2(wp3, a6, A.a[3][6]);
        A.a[3][7] = ffma2(wp3, a7, A.a[3][7]);
    }
}

__device__ __forceinline__ void mm_pass(Acc& A, const float* __restrict__ wp,
                                        const float* __restrict__ ap1,
                                        const float* __restrict__ ap2) {
    mm_half(A, wp, ap1);
    mm_half(A, wp + 8 * WSTR, ap2);
}

// 3-level exchange-halving k-reduction across kq (lane bits 2,3,4).
// Final: v[0..7] = full sums for row j0+kq, cols m0..m0+7. 56 shfl total.
__device__ __forceinline__ void reduce_select(Acc& A, int kq, float (&v)[8]) {
    u64 B[2][8];
#pragma unroll
    for (int p = 0; p < 2; ++p)
#pragma unroll
        for (int m = 0; m < 8; ++m) {
            const u64 snd = (kq & 4) ? A.a[p][m] : A.a[p + 2][m];
            const u64 kpt = (kq & 4) ? A.a[p + 2][m] : A.a[p][m];
            float sl, sh, kl, kh;
            unpack2(snd, sl, sh);
            sl = __shfl_xor_sync(0xffffffffu, sl, 16);
            sh = __shfl_xor_sync(0xffffffffu, sh, 16);
            unpack2(kpt, kl, kh);
            B[p][m] = pack2(kl + sl, kh + sh);
        }
    u64 C[8];
#pragma unroll
    for (int m = 0; m < 8; ++m) {
        const u64 snd = (kq & 2) ? B[0][m] : B[1][m];
        const u64 kpt = (kq & 2) ? B[1][m] : B[0][m];
        float sl, sh, kl, kh;
        unpack2(snd, sl, sh);
        sl = __shfl_xor_sync(0xffffffffu, sl, 8);
        sh = __shfl_xor_sync(0xffffffffu, sh, 8);
        unpack2(kpt, kl, kh);
        C[m] = pack2(kl + sl, kh + sh);
    }
#pragma unroll
    for (int m = 0; m < 8; ++m) {
        float lo, hi;
        unpack2(C[m], lo, hi);
        const float snd = (kq & 1) ? lo : hi;
        const float kpt = (kq & 1) ? hi : lo;
        v[m] = kpt + __shfl_xor_sync(0xffffffffu, snd, 4);
    }
}

// bias + optional residual + leaky + store row j0+kq, cols m0..m0+7.
__device__ __forceinline__ void epi(Acc& A, const float* __restrict__ bias,
                                    float* __restrict__ dst, bool hasRes,
                                    int r, int m0, int kq) {
    float v[8];
    reduce_select(A, kq, v);
    const float bv = __ldg(bias + r);
#pragma unroll
    for (int m = 0; m < 8; ++m) v[m] += bv;
    const int ao = act_addr(r, m0);
    if (hasRes) {
        const float4 rA = *reinterpret_cast<const float4*>(dst + ao);
        const float4 rB = *reinterpret_cast<const float4*>(dst + ao + 4);
        v[0] += rA.x; v[1] += rA.y; v[2] += rA.z; v[3] += rA.w;
        v[4] += rB.x; v[5] += rB.y; v[6] += rB.z; v[7] += rB.w;
    }
#pragma unroll
    for (int m = 0; m < 8; ++m) v[m] = fmaxf(v[m], NEGS * v[m]);
    *reinterpret_cast<float4*>(dst + ao)     = make_float4(v[0], v[1], v[2], v[3]);
    *reinterpret_cast<float4*>(dst + ao + 4) = make_float4(v[4], v[5], v[6], v[7]);
}

template <bool RES>
__device__ __forceinline__ void full_layer(const float* __restrict__ Wsm,
                                           const float* __restrict__ b,
                                           const float* __restrict__ hin,
                                           float* __restrict__ hout,
                                           int wofs, int aofs1, int aofs2,
                                           int r, int m0, int kq) {
    Acc A; acc_zero(A);
    mm_pass(A, Wsm + wofs, hin + aofs1, hin + aofs2);
    epi(A, b, hout, RES, r, m0, kq);
}

// Small-K input layer: thread computes row r = j0+kq, cols m0..m0+7.
__device__ __forceinline__ void input_layer(const float* __restrict__ Win,
                                            const float* __restrict__ bin,
                                            const float* __restrict__ xsT,
                                            int coff, int K,
                                            float* __restrict__ dst,
                                            int r, int m0) {
    float y[8] = {};
    for (int k = 0; k < K; ++k) {
        const float wv = __ldg(Win + k * HID + r);
        const float4 aA = *reinterpret_cast<const float4*>(xsT + (coff + k) * 16 + m0);
        const float4 aB = *reinterpret_cast<const float4*>(xsT + (coff + k) * 16 + m0 + 4);
        y[0] = fmaf(wv, aA.x, y[0]); y[1] = fmaf(wv, aA.y, y[1]);
        y[2] = fmaf(wv, aA.z, y[2]); y[3] = fmaf(wv, aA.w, y[3]);
        y[4] = fmaf(wv, aB.x, y[4]); y[5] = fmaf(wv, aB.y, y[5]);
        y[6] = fmaf(wv, aB.z, y[6]); y[7] = fmaf(wv, aB.w, y[7]);
    }
    const float bv = __ldg(bin + r);
#pragma unroll
    for (int i = 0; i < 8; ++i) {
        y[i] += bv;
        y[i] = fmaxf(y[i], NEGS * y[i]);
    }
    const int ao = act_addr(r, m0);
    *reinterpret_cast<float4*>(dst + ao)     = make_float4(y[0], y[1], y[2], y[3]);
    *reinterpret_cast<float4*>(dst + ao + 4) = make_float4(y[4], y[5], y[6], y[7]);
}

__global__ void __launch_bounds__(NTHR, 1)
hedger_kernel(const float* __restrict__ feats,
              const float* __restrict__ fw_in, const float* __restrict__ fb_in,
              const float* __restrict__ fr1_w1, const float* __restrict__ fr1_b1,
              const float* __restrict__ fr1_w2, const float* __restrict__ fr1_b2,
              const float* __restrict__ fr2_w1, const float* __restrict__ fr2_b1,
              const float* __restrict__ fr2_w2, const float* __restrict__ fr2_b2,
              const float* __restrict__ pw_in, const float* __restrict__ pb_in,
              const float* __restrict__ pr1_w1, const float* __restrict__ pr1_b1,
              const float* __restrict__ pr1_w2, const float* __restrict__ pr1_b2,
              const float* __restrict__ pr2_w1, const float* __restrict__ pr2_b1,
              const float* __restrict__ pr2_w2, const float* __restrict__ pr2_b2,
              const float* __restrict__ cw1, const float* __restrict__ cb1,
              const float* __restrict__ cw2, const float* __restrict__ cb2,
              float* __restrict__ out) {
    extern __shared__ float sm[];
    float* wb0  = sm + WB0;
    float* wb1  = sm + WB1;
    float* hb_f = sm + HB_F;
    float* ht_f = sm + HT_F;
    float* hb_p = sm + HB_P;
    float* ht_p = sm + HT_P;
    float* xsT  = sm + XST;
    float* ds   = sm + DSO;

    const int tid  = threadIdx.x;
    const int lane = tid & 31;
    const int w    = tid >> 5;
    const int kq   = lane >> 2;                   // 0..7 k-eighth
    const int pos2 = lane & 3;
    const int j0   = (w & 3) * 32 + pos2 * 8;     // 8-row j block
    const int m0   = (w >> 2) * 8;                // m-octet
    const int b0   = blockIdx.x * MROWS;
    const int r    = j0 + kq;                     // this thread's epilogue row

    // per-thread affine bases (swizzles resolved once)
    const int wofs  = kq * 16 * WSTR + (kq & 1) * 4 + j0;
    const int aofs1 = act_addr(kq * 16, m0);        // rows kq*16 .. +7
    const int aofs2 = act_addr(kq * 16 + 8, m0);    // rows kq*16+8 .. +15

    const float cb2v = __ldg(cb2);
    const float* cw1_hi = cw1 + HID * HID;

    prefetch_w(fr1_w1, wb0, tid);
    cp_commit();

    for (int n = 0; n < NSTEP; ++n) {
        // ---- features -> xsT[c][m]; recurrent delta into col 3 ----
        if (tid < MROWS * 12) {
            const int rr = tid / 12, c = tid % 12;
            float vv = feats[((size_t)(b0 + rr) * NSTEP + n) * 12 + c];
            if (c == 3 && n > 0) vv = ds[rr];
            xsT[c * 16 + rr] = vv;
        }
        __syncthreads();

        // ---- input layers (tiny K, weights L1-resident) ----
        input_layer(fw_in, fb_in, xsT, 0, 4, hb_f, r, m0);
        input_layer(pw_in, pb_in, xsT, 4, 8, hb_p, r, m0);

        // ---- 10 staged 64KB layers, double-buffered ----
        cp_wait_all(); __syncthreads();
        prefetch_w(fr1_w2, wb1, tid); cp_commit();
        full_layer<false>(wb0, fr1_b1, hb_f, ht_f, wofs, aofs1, aofs2, r, m0, kq);

        cp_wait_all(); __syncthreads();
        prefetch_w(fr2_w1, wb0, tid); cp_commit();
        full_layer<true >(wb1, fr1_b2, ht_f, hb_f, wofs, aofs1, aofs2, r, m0, kq);

        cp_wait_all(); __syncthreads();
        prefetch_w(fr2_w2, wb1, tid); cp_commit();
        full_layer<false>(wb0, fr2_b1, hb_f, ht_f, wofs, aofs1, aofs2, r, m0, kq);

        cp_wait_all(); __syncthreads();
        prefetch_w(pr1_w1, wb0, tid); cp_commit();
        full_layer<true >(wb1, fr2_b2, ht_f, hb_f, wofs, aofs1, aofs2, r, m0, kq);

        cp_wait_all(); __syncthreads();
        prefetch_w(pr1_w2, wb1, tid); cp_commit();
        full_layer<false>(wb0, pr1_b1, hb_p, ht_p, wofs, aofs1, aofs2, r, m0, kq);

        cp_wait_all(); __syncthreads();
        prefetch_w(pr2_w1, wb0, tid); cp_commit();
        full_layer<true >(wb1, pr1_b2, ht_p, hb_p, wofs, aofs1, aofs2, r, m0, kq);

        cp_wait_all(); __syncthreads();
        prefetch_w(pr2_w2, wb1, tid); cp_commit();
        full_layer<false>(wb0, pr2_b1, hb_p, ht_p, wofs, aofs1, aofs2, r, m0, kq);

        cp_wait_all(); __syncthreads();
        prefetch_w(cw1, wb0, tid); cp_commit();
        full_layer<true >(wb1, pr2_b2, ht_p, hb_p, wofs, aofs1, aofs2, r, m0, kq);

        // combiner: accumulate both halves of concat(fe, pe) @ cw1
        {
            Acc A; acc_zero(A);
            cp_wait_all(); __syncthreads();
            prefetch_w(cw1_hi, wb1, tid); cp_commit();
            mm_pass(A, wb0 + wofs, hb_f + aofs1, hb_f + aofs2);   // fe @ cw1[0:128]

            cp_wait_all(); __syncthreads();
            prefetch_w(fr1_w1, wb0, tid); cp_commit();            // wrap: next step's L0
            mm_pass(A, wb1 + wofs, hb_p + aofs1, hb_p + aofs2);   // pe @ cw1[128:256]
            epi(A, cb1, ht_f, false, r, m0, kq);
        }
        __syncthreads();

        // ---- head: sigmoid(hc @ cw2 + cb2) ----
        if (tid < 128) {
            const int m   = tid >> 3;        // 0..15
            const int seg = tid & 7;         // 8-way j split
            float pacc = 0.0f;
#pragma unroll
            for (int jj = 0; jj < 16; ++jj) {
                const int j = jj * 8 + seg;
                pacc += ht_f[act_addr(j, m)] * __ldg(cw2 + j);
            }
            pacc += __shfl_down_sync(0xffffffffu, pacc, 4, 8);
            pacc += __shfl_down_sync(0xffffffffu, pacc, 2, 8);
            pacc += __shfl_down_sync(0xffffffffu, pacc, 1, 8);
            if (seg == 0) {
                const float d = 1.0f / (1.0f + expf(-(pacc + cb2v)));
                ds[m] = d;
                out[(size_t)(b0 + m) * NSTEP + n] = d;
            }
        }
        __syncthreads();
    }
}

extern "C" void kernel_launch(void* const* d_in, const int* in_sizes, int n_in,
                              void* d_out, int out_size) {
    const float* feats  = (const float*)d_in[0];
    const float* fw_in  = (const float*)d_in[1];
    const float* fb_in  = (const float*)d_in[2];
    const float* fr1_w1 = (const float*)d_in[3];
    const float* fr1_b1 = (const float*)d_in[4];
    const float* fr1_w2 = (const float*)d_in[5];
    const float* fr1_b2 = (const float*)d_in[6];
    const float* fr2_w1 = (const float*)d_in[7];
    const float* fr2_b1 = (const float*)d_in[8];
    const float* fr2_w2 = (const float*)d_in[9];
    const float* fr2_b2 = (const float*)d_in[10];
    const float* pw_in  = (const float*)d_in[11];
    const float* pb_in  = (const float*)d_in[12];
    const float* pr1_w1 = (const float*)d_in[13];
    const float* pr1_b1 = (const float*)d_in[14];
    const float* pr1_w2 = (const float*)d_in[15];
    const float* pr1_b2 = (const float*)d_in[16];
    const float* pr2_w1 = (const float*)d_in[17];
    const float* pr2_b1 = (const float*)d_in[18];
    const float* pr2_w2 = (const float*)d_in[19];
    const float* pr2_b2 = (const float*)d_in[20];
    const float* cw1    = (const float*)d_in[21];
    const float* cb1    = (const float*)d_in[22];
    const float* cw2    = (const float*)d_in[23];
    const float* cb2    = (const float*)d_in[24];

    cudaFuncSetAttribute(hedger_kernel,
                         cudaFuncAttributeMaxDynamicSharedMemorySize, SMEM_BYTES);

    hedger_kernel<<<2048 / MROWS, NTHR, SMEM_BYTES>>>(
        feats,
        fw_in, fb_in,
        fr1_w1, fr1_b1, fr1_w2, fr1_b2,
        fr2_w1, fr2_b1, fr2_w2, fr2_b2,
        pw_in, pb_in,
        pr1_w1, pr1_b1, pr1_w2, pr1_b2,
        pr2_w1, pr2_b1, pr2_w2, pr2_b2,
        cw1, cb1, cw2, cb2,
        (float*)d_out);
}